// round 11
// baseline (speedup 1.0000x reference)
#include <cuda_runtime.h>
#include <math.h>

#define DIM 128
#define NMAX 50000
#define NCMAX 1600   // 32-row chunks

// ---------------- scratch (allocation-free) ----------------
static constexpr size_t SZ_ND   = (size_t)NMAX * DIM;          // 6,400,000
static constexpr size_t SZ_PQ   = (size_t)NCMAX * DIM;         // 204,800
static constexpr size_t OFF_SUMS = 0;
static constexpr size_t OFF_CNT  = OFF_SUMS + SZ_ND;
static constexpr size_t OFF_X0   = OFF_CNT + 50048;
static constexpr size_t OFF_X1   = OFF_X0 + SZ_ND;
static constexpr size_t OFF_A    = OFF_X1 + SZ_ND;
static constexpr size_t OFF_B    = OFF_A + SZ_ND;
static constexpr size_t OFF_P    = OFF_B + SZ_ND;
static constexpr size_t OFF_Q    = OFF_P + SZ_PQ;
static constexpr size_t OFF_C    = OFF_Q + SZ_PQ;
static constexpr size_t SCRATCH_TOTAL = OFF_C + SZ_PQ;

__device__ __align__(16) float g_scratch[SCRATCH_TOTAL];

// ---------------- f32x2 packed helpers (sm_10x) ----------------
typedef unsigned long long u64;

__device__ __forceinline__ u64 dup2(float v) {
    u64 r;
    asm("mov.b64 %0, {%1, %1};" : "=l"(r) : "f"(v));
    return r;
}
__device__ __forceinline__ void fma2(u64& d, u64 a, u64 b) {
    asm("fma.rn.f32x2 %0, %1, %2, %0;" : "+l"(d) : "l"(a), "l"(b));
}
__device__ __forceinline__ float2 unpack2(u64 v) {
    float2 f;
    asm("mov.b64 {%0, %1}, %2;" : "=f"(f.x), "=f"(f.y) : "l"(v));
    return f;
}

// ---------------- kernels ----------------

__global__ void k_zero(float* __restrict__ sums, float* __restrict__ cnt, int N) {
    size_t i = (size_t)blockIdx.x * blockDim.x + threadIdx.x;
    size_t stride = (size_t)gridDim.x * blockDim.x;
    size_t n4 = (size_t)N * DIM / 4;
    float4 z = make_float4(0.f, 0.f, 0.f, 0.f);
    for (size_t k = i; k < n4; k += stride) ((float4*)sums)[k] = z;
    for (size_t k = i; k < (size_t)N; k += stride) cnt[k] = 0.f;
}

// warp-per-edge gather + vector atomic scatter
__global__ void k_scatter(const int* __restrict__ ei, const int* __restrict__ et,
                          const int* __restrict__ tt, const float* __restrict__ ew,
                          const float* __restrict__ ent, const float* __restrict__ rel,
                          const float* __restrict__ tim,
                          float* __restrict__ sums, float* __restrict__ cnt, int E) {
    int e = (int)(((size_t)blockIdx.x * blockDim.x + threadIdx.x) >> 5);
    if (e >= E) return;
    int lane = threadIdx.x & 31;
    int src = ei[e], dst = ei[E + e];
    int r = et[e], ti = tt[e];
    float w = ew[e];
    float4 a = ((const float4*)(ent + (size_t)src * DIM))[lane];
    float4 b = ((const float4*)(rel + (size_t)r * DIM))[lane];
    float4 c = ((const float4*)(tim + (size_t)ti * DIM))[lane];
    float4 m;
    m.x = (a.x + b.x + c.x) * w;
    m.y = (a.y + b.y + c.y) * w;
    m.z = (a.z + b.z + c.z) * w;
    m.w = (a.w + b.w + c.w) * w;
    atomicAdd(((float4*)(sums + (size_t)dst * DIM)) + lane, m);
    if (lane == 0) atomicAdd(cnt + dst, w);
}

// warp-per-row: mean, L2-normalize, permute-gather
__global__ void k_normperm(const int* __restrict__ perm, const float* __restrict__ sums,
                           const float* __restrict__ cnt, float* __restrict__ xo, int N) {
    int row = (int)(((size_t)blockIdx.x * blockDim.x + threadIdx.x) >> 5);
    if (row >= N) return;
    int lane = threadIdx.x & 31;
    int p = perm[row];
    float inv = 1.f / fmaxf(cnt[p], 1.f);
    float4 v = ((const float4*)(sums + (size_t)p * DIM))[lane];
    v.x *= inv; v.y *= inv; v.z *= inv; v.w *= inv;
    float sq = v.x * v.x + v.y * v.y + v.z * v.z + v.w * v.w;
#pragma unroll
    for (int o = 16; o > 0; o >>= 1) sq += __shfl_xor_sync(0xffffffffu, sq, o);
    float s = 1.f / fmaxf(sqrtf(sq), 1e-12f);
    v.x *= s; v.y *= s; v.z *= s; v.w *= s;
    ((float4*)(xo + (size_t)row * DIM))[lane] = v;
}

__device__ __forceinline__ float sigmoidf_fast(float v) {
    return 1.f / (1.f + __expf(-v));
}

// zg = x @ Wi + bi ; a = sigmoid(g)*A[d] ; b = B[d]*z ; ALSO emits per-32-row-chunk (P,Q).
// 256 threads: jg = t&31 (4 z + 4 g cols), rg = t>>5 (8 rows each) -> 64 rows/tile.
__global__ void __launch_bounds__(256, 1) k_inproj(
    const float* __restrict__ x, const float* __restrict__ Wi, const float* __restrict__ bi,
    const float* __restrict__ Av, const float* __restrict__ Bv,
    float* __restrict__ aout, float* __restrict__ bout,
    float* __restrict__ Pb, float* __restrict__ Qb, int N, int NC) {
    extern __shared__ __align__(16) char smraw[];
    u64* x_dup = (u64*)smraw;                              // 64*128 u64 = 65536 B
    float* w_sm = (float*)(smraw + 65536);                 // 32768 f   = 131072 B
    float* bi_sm = (float*)(smraw + 65536 + 131072);       // 256 f
    float* A_sm = bi_sm + 256;                             // 128 f
    float* B_sm = A_sm + 128;                              // 128 f
    float* pq_sm = B_sm + 128;                             // 2048 f (p[8][32][4], q at +1024)
    int t = threadIdx.x;
    for (int k = t; k < 8192; k += 256) ((float4*)w_sm)[k] = ((const float4*)Wi)[k];
    if (t < 64) ((float4*)bi_sm)[t] = ((const float4*)bi)[t];
    if (t < 32) ((float4*)A_sm)[t] = ((const float4*)Av)[t];
    else if (t < 64) ((float4*)B_sm)[t - 32] = ((const float4*)Bv)[t - 32];
    __syncthreads();
    int jg = t & 31, rg = t >> 5;
    int ntiles = (N + 63) >> 6;
    for (int tile = blockIdx.x; tile < ntiles; tile += gridDim.x) {
        int row0 = tile << 6;
        __syncthreads();
        for (int k = t; k < 2048; k += 256) {
            int row = k >> 5;
            float4 v = make_float4(0.f, 0.f, 0.f, 0.f);
            if (row0 + row < N) v = ((const float4*)x)[(size_t)row0 * 32 + k];
            ulonglong2* dst = (ulonglong2*)(x_dup + (size_t)row * DIM + (k & 31) * 4);
            dst[0] = make_ulonglong2(dup2(v.x), dup2(v.y));
            dst[1] = make_ulonglong2(dup2(v.z), dup2(v.w));
        }
        __syncthreads();
        u64 az[8][2], ag[8][2];
#pragma unroll
        for (int r = 0; r < 8; r++) {
            az[r][0] = 0ull; az[r][1] = 0ull;
            ag[r][0] = 0ull; ag[r][1] = 0ull;
        }
        const u64* xr = x_dup + (size_t)(rg * 8) * DIM;
        for (int d = 0; d < DIM; d += 2) {
            ulonglong2 wz0 = ((const ulonglong2*)(w_sm + d * 256))[jg];
            ulonglong2 wg0 = ((const ulonglong2*)(w_sm + d * 256 + 128))[jg];
            ulonglong2 wz1 = ((const ulonglong2*)(w_sm + (d + 1) * 256))[jg];
            ulonglong2 wg1 = ((const ulonglong2*)(w_sm + (d + 1) * 256 + 128))[jg];
#pragma unroll
            for (int r = 0; r < 8; r++) {
                ulonglong2 xx = *((const ulonglong2*)(xr + r * DIM + d));  // x[d], x[d+1] dup'd
                fma2(az[r][0], wz0.x, xx.x);
                fma2(az[r][1], wz0.y, xx.x);
                fma2(ag[r][0], wg0.x, xx.x);
                fma2(ag[r][1], wg0.y, xx.x);
                fma2(az[r][0], wz1.x, xx.y);
                fma2(az[r][1], wz1.y, xx.y);
                fma2(ag[r][0], wg1.x, xx.y);
                fma2(ag[r][1], wg1.y, xx.y);
            }
        }
        float4 bz = ((const float4*)bi_sm)[jg];
        float4 bg = ((const float4*)bi_sm)[jg + 32];
        float4 B4 = ((const float4*)B_sm)[jg];
        float4 A4 = ((const float4*)A_sm)[jg];
        float p0 = 1.f, p1 = 1.f, p2 = 1.f, p3 = 1.f;
        float q0 = 0.f, q1 = 0.f, q2 = 0.f, q3 = 0.f;
#pragma unroll
        for (int r = 0; r < 8; r++) {   // ascending rows -> correct scan order
            int row = row0 + rg * 8 + r;
            float2 z0 = unpack2(az[r][0]);
            float2 z1 = unpack2(az[r][1]);
            float2 g0 = unpack2(ag[r][0]);
            float2 g1 = unpack2(ag[r][1]);
            float4 ob, oa;
            ob.x = B4.x * (z0.x + bz.x);
            ob.y = B4.y * (z0.y + bz.y);
            ob.z = B4.z * (z1.x + bz.z);
            ob.w = B4.w * (z1.y + bz.w);
            oa.x = A4.x * sigmoidf_fast(g0.x + bg.x);
            oa.y = A4.y * sigmoidf_fast(g0.y + bg.y);
            oa.z = A4.z * sigmoidf_fast(g1.x + bg.z);
            oa.w = A4.w * sigmoidf_fast(g1.y + bg.w);
            if (row < N) {
                ((float4*)(bout + (size_t)row * DIM))[jg] = ob;
                ((float4*)(aout + (size_t)row * DIM))[jg] = oa;
            } else {   // identity element for the chunk product
                oa = make_float4(1.f, 1.f, 1.f, 1.f);
                ob = make_float4(0.f, 0.f, 0.f, 0.f);
            }
            q0 = fmaf(oa.x, q0, ob.x); p0 *= oa.x;
            q1 = fmaf(oa.y, q1, ob.y); p1 *= oa.y;
            q2 = fmaf(oa.z, q2, ob.z); p2 *= oa.z;
            q3 = fmaf(oa.w, q3, ob.w); p3 *= oa.w;
        }
        ((float4*)pq_sm)[rg * 32 + jg] = make_float4(p0, p1, p2, p3);
        ((float4*)(pq_sm + 1024))[rg * 32 + jg] = make_float4(q0, q1, q2, q3);
        __syncthreads();
        {   // combine 4 warp-partials per 32-row chunk; 2 chunks x 128 dims = 256 threads
            int chunkLocal = t >> 7;
            int dim = t & 127;
            int gchunk = tile * 2 + chunkLocal;
            if (gchunk < NC) {
                int jj = dim >> 2, cc = dim & 3;
                float P = 1.f, Q = 0.f;
#pragma unroll
                for (int s = 0; s < 4; s++) {
                    int rr = chunkLocal * 4 + s;
                    float pp = pq_sm[(rr * 32 + jj) * 4 + cc];
                    float qq = pq_sm[1024 + (rr * 32 + jj) * 4 + cc];
                    Q = fmaf(pp, Q, qq);
                    P *= pp;
                }
                Pb[(size_t)gchunk * DIM + dim] = P;
                Qb[(size_t)gchunk * DIM + dim] = Q;
            }
        }
    }
}

// compose 32-row-chunk carries (single block; smem-staged, register-grouped chain)
__global__ void k_carry(const float* __restrict__ P, const float* __restrict__ Q,
                        float* __restrict__ C, int NC) {
    extern __shared__ float sm[];
    float* Ps = sm;
    float* Qs = sm + 64 * DIM;
    int d = threadIdx.x;
    float h = 0.f;
    for (int base = 0; base < NC; base += 64) {
        int cnt = min(64, NC - base);
        __syncthreads();
        for (int k = d; k < cnt * DIM; k += DIM) {
            Ps[k] = P[base * DIM + k];
            Qs[k] = Q[base * DIM + k];
        }
        __syncthreads();
        for (int k0 = 0; k0 < cnt; k0 += 4) {
            float p[4], q[4];
#pragma unroll
            for (int j = 0; j < 4; j++) {
                if (k0 + j < cnt) {
                    p[j] = Ps[(k0 + j) * DIM + d];
                    q[j] = Qs[(k0 + j) * DIM + d];
                } else { p[j] = 1.f; q[j] = 0.f; }
            }
#pragma unroll
            for (int j = 0; j < 4; j++) {
                if (k0 + j < cnt) C[(size_t)(base + k0 + j) * DIM + d] = h;
                h = fmaf(p[j], h, q[j]);
            }
        }
    }
}

// Fused: scan(a,b with carry) -> h ; y = x + h@Wo + bo ; LayerNorm -> xo.
// Tile = 32 rows = one carry chunk. 256 threads: jg = t&31 (4 cols), rg = t>>5 (4 rows).
__global__ void __launch_bounds__(256, 2) k_outscan(
    const float* __restrict__ x, const float* __restrict__ ain, const float* __restrict__ bin,
    const float* __restrict__ Cb,
    const float* __restrict__ Wo, const float* __restrict__ bo,
    const float* __restrict__ lng, const float* __restrict__ lnb,
    float* __restrict__ xo, int N) {
    extern __shared__ __align__(16) char smraw[];
    float* w_sm = (float*)smraw;                       // 16384 f = 65536 B
    float* a_sm = (float*)(smraw + 65536);             // 32*128 f = 16384 B
    float* b_sm = (float*)(smraw + 65536 + 16384);     // 32*128 f = 16384 B (becomes h)
    float* bo_sm = (float*)(smraw + 65536 + 32768);    // 128 f
    float* g_sm = bo_sm + 128;
    float* be_sm = g_sm + 128;
    int t = threadIdx.x;
    for (int k = t; k < 4096; k += 256) ((float4*)w_sm)[k] = ((const float4*)Wo)[k];
    if (t < 32) ((float4*)bo_sm)[t] = ((const float4*)bo)[t];
    else if (t < 64) ((float4*)g_sm)[t - 32] = ((const float4*)lng)[t - 32];
    else if (t < 96) ((float4*)be_sm)[t - 64] = ((const float4*)lnb)[t - 64];
    __syncthreads();
    int jg = t & 31, rg = t >> 5;
    int ntiles = (N + 31) >> 5;
    for (int tile = blockIdx.x; tile < ntiles; tile += gridDim.x) {
        int row0 = tile << 5;
        __syncthreads();
        for (int k = t; k < 1024; k += 256) {
            int row = k >> 5;
            float4 va = make_float4(0.f, 0.f, 0.f, 0.f);
            float4 vb = va;
            if (row0 + row < N) {
                va = ((const float4*)ain)[(size_t)row0 * 32 + k];
                vb = ((const float4*)bin)[(size_t)row0 * 32 + k];
            }
            ((float4*)a_sm)[k] = va;
            ((float4*)b_sm)[k] = vb;
        }
        __syncthreads();
        if (t < DIM) {   // sequential scan over the 32 rows of this chunk; h overwrites b_sm
            float hv = Cb[(size_t)tile * DIM + t];
#pragma unroll 8
            for (int r = 0; r < 32; r++) {
                hv = fmaf(a_sm[r * DIM + t], hv, b_sm[r * DIM + t]);
                b_sm[r * DIM + t] = hv;
            }
        }
        __syncthreads();
        u64 acc[4][2];
#pragma unroll
        for (int r = 0; r < 4; r++) { acc[r][0] = 0ull; acc[r][1] = 0ull; }
        const float* hr = b_sm + (size_t)(rg * 4) * DIM;
        for (int d = 0; d < DIM; d += 2) {
            ulonglong2 wv0 = ((const ulonglong2*)(w_sm + d * DIM))[jg];
            ulonglong2 wv1 = ((const ulonglong2*)(w_sm + (d + 1) * DIM))[jg];
#pragma unroll
            for (int r = 0; r < 4; r++) {
                float2 hh = *((const float2*)(hr + r * DIM + d));
                u64 h0 = dup2(hh.x);
                u64 h1 = dup2(hh.y);
                fma2(acc[r][0], wv0.x, h0);
                fma2(acc[r][1], wv0.y, h0);
                fma2(acc[r][0], wv1.x, h1);
                fma2(acc[r][1], wv1.y, h1);
            }
        }
        float4 b4 = ((const float4*)bo_sm)[jg];
        float4 g4 = ((const float4*)g_sm)[jg];
        float4 e4 = ((const float4*)be_sm)[jg];
#pragma unroll
        for (int r = 0; r < 4; r++) {
            int row = row0 + rg * 4 + r;
            if (row < N) {   // uniform across the warp
                float2 a0 = unpack2(acc[r][0]);
                float2 a1 = unpack2(acc[r][1]);
                float4 xv = ((const float4*)x)[(size_t)row * 32 + jg];
                float4 y;
                y.x = a0.x + b4.x + xv.x;
                y.y = a0.y + b4.y + xv.y;
                y.z = a1.x + b4.z + xv.z;
                y.w = a1.y + b4.w + xv.w;
                float s = y.x + y.y + y.z + y.w;
                float sq = y.x * y.x + y.y * y.y + y.z * y.z + y.w * y.w;
#pragma unroll
                for (int o = 16; o > 0; o >>= 1) {
                    s += __shfl_xor_sync(0xffffffffu, s, o);
                    sq += __shfl_xor_sync(0xffffffffu, sq, o);
                }
                float mu = s * (1.f / 128.f);
                float var = sq * (1.f / 128.f) - mu * mu;
                float rs = rsqrtf(var + 1e-5f);
                float4 o4;
                o4.x = (y.x - mu) * rs * g4.x + e4.x;
                o4.y = (y.y - mu) * rs * g4.y + e4.y;
                o4.z = (y.z - mu) * rs * g4.z + e4.z;
                o4.w = (y.w - mu) * rs * g4.w + e4.w;
                ((float4*)(xo + (size_t)row * DIM))[jg] = o4;
            }
        }
    }
}

// ---------------- launch ----------------
static constexpr int SMEM_IN = 65536 + 131072 + (256 + 128 + 128 + 2048) * 4;  // 206,848 B
static constexpr int SMEM_OUT = 65536 + 16384 + 16384 + (128 + 128 + 128) * 4; // 99,840 B

extern "C" void kernel_launch(void* const* d_in, const int* in_sizes, int n_in,
                              void* d_out, int out_size) {
    const int* edge_index = (const int*)d_in[0];
    const int* edge_type = (const int*)d_in[1];
    const int* edge_time = (const int*)d_in[2];
    const float* edge_weight = (const float*)d_in[3];
    const int* perm = (const int*)d_in[4];
    const float* ent = (const float*)d_in[5];
    const float* rel = (const float*)d_in[6];
    const float* tim = (const float*)d_in[7];
    const float* Wi = (const float*)d_in[8];
    const float* bi = (const float*)d_in[9];
    const float* Wo = (const float*)d_in[10];
    const float* bo = (const float*)d_in[11];
    const float* Av = (const float*)d_in[12];
    const float* Bv = (const float*)d_in[13];
    const float* lng = (const float*)d_in[14];
    const float* lnb = (const float*)d_in[15];
    float* out = (float*)d_out;

    int E = in_sizes[1];
    int N = in_sizes[4];
    int L = in_sizes[12] / DIM;

    float* base = nullptr;
    cudaGetSymbolAddress((void**)&base, g_scratch);
    float* sums = base + OFF_SUMS;
    float* cnt = base + OFF_CNT;
    float* x0 = base + OFF_X0;
    float* x1 = base + OFF_X1;
    float* ab_a = base + OFF_A;
    float* ab_b = base + OFF_B;
    float* Pb = base + OFF_P;
    float* Qb = base + OFF_Q;
    float* Cb = base + OFF_C;

    cudaFuncSetAttribute(k_inproj, cudaFuncAttributeMaxDynamicSharedMemorySize, SMEM_IN);
    cudaFuncSetAttribute(k_outscan, cudaFuncAttributeMaxDynamicSharedMemorySize, SMEM_OUT);
    cudaFuncSetAttribute(k_carry, cudaFuncAttributeMaxDynamicSharedMemorySize, 65536);

    k_zero<<<2048, 256>>>(sums, cnt, N);

    int sblocks = (int)(((size_t)E * 32 + 255) / 256);
    k_scatter<<<sblocks, 256>>>(edge_index, edge_type, edge_time, edge_weight,
                                ent, rel, tim, sums, cnt, E);

    k_normperm<<<(N + 7) / 8, 256>>>(perm, sums, cnt, x0, N);

    int NC = (N + 31) / 32;   // 32-row chunks
    float* ping[2] = {x0, x1};
    const float* xin = x0;
    for (int l = 0; l < L; l++) {
        k_inproj<<<152, 256, SMEM_IN>>>(xin, Wi + (size_t)l * DIM * 2 * DIM,
                                        bi + (size_t)l * 2 * DIM,
                                        Av + (size_t)l * DIM, Bv + (size_t)l * DIM,
                                        ab_a, ab_b, Pb, Qb, N, NC);
        k_carry<<<1, DIM, 65536>>>(Pb, Qb, Cb, NC);
        float* xout = (l == L - 1) ? out : ping[(l + 1) & 1];
        k_outscan<<<304, 256, SMEM_OUT>>>(xin, ab_a, ab_b, Cb,
                                          Wo + (size_t)l * DIM * DIM,
                                          bo + (size_t)l * DIM,
                                          lng + (size_t)l * DIM, lnb + (size_t)l * DIM,
                                          xout, N);
        xin = xout;
    }
}

// round 12
// speedup vs baseline: 1.2279x; 1.2279x over previous
#include <cuda_runtime.h>
#include <math.h>

#define DIM 128
#define NMAX 50000
#define NROW_PAD 50048          // NMAX rounded up to 64
#define NCMAX 800               // 64-row chunks (782 needed)

// ---------------- scratch (allocation-free) ----------------
static constexpr size_t SZ_ND   = (size_t)NROW_PAD * DIM;      // 6,406,144
static constexpr size_t SZ_HT   = (size_t)NCMAX * 8192;        // 6,553,600
static constexpr size_t OFF_SUMS = 0;
static constexpr size_t OFF_CNT  = OFF_SUMS + SZ_ND;
static constexpr size_t OFF_X0   = OFF_CNT + NROW_PAD;
static constexpr size_t OFF_X1   = OFF_X0 + SZ_ND;
static constexpr size_t OFF_A    = OFF_X1 + SZ_ND;
static constexpr size_t OFF_B    = OFF_A + SZ_ND;
static constexpr size_t OFF_HT   = OFF_B + SZ_ND;
static constexpr size_t OFF_P    = OFF_HT + SZ_HT;
static constexpr size_t OFF_Q    = OFF_P + (size_t)NCMAX * DIM;
static constexpr size_t OFF_C    = OFF_Q + (size_t)NCMAX * DIM;
static constexpr size_t SCRATCH_TOTAL = OFF_C + (size_t)NCMAX * DIM;

__device__ __align__(16) float g_scratch[SCRATCH_TOTAL];

// ---------------- f32x2 packed helpers (sm_10x) ----------------
typedef unsigned long long u64;

__device__ __forceinline__ u64 dup2(float v) {
    u64 r;
    asm("mov.b64 %0, {%1, %1};" : "=l"(r) : "f"(v));
    return r;
}
__device__ __forceinline__ void fma2(u64& d, u64 a, u64 b) {
    asm("fma.rn.f32x2 %0, %1, %2, %0;" : "+l"(d) : "l"(a), "l"(b));
}
__device__ __forceinline__ float2 unpack2(u64 v) {
    float2 f;
    asm("mov.b64 {%0, %1}, %2;" : "=f"(f.x), "=f"(f.y) : "l"(v));
    return f;
}

// ---------------- kernels ----------------

__global__ void k_zero(float* __restrict__ sums, float* __restrict__ cnt, int N) {
    size_t i = (size_t)blockIdx.x * blockDim.x + threadIdx.x;
    size_t stride = (size_t)gridDim.x * blockDim.x;
    size_t n4 = (size_t)N * DIM / 4;
    float4 z = make_float4(0.f, 0.f, 0.f, 0.f);
    for (size_t k = i; k < n4; k += stride) ((float4*)sums)[k] = z;
    for (size_t k = i; k < (size_t)N; k += stride) cnt[k] = 0.f;
}

// warp-per-edge gather + vector atomic scatter
__global__ void k_scatter(const int* __restrict__ ei, const int* __restrict__ et,
                          const int* __restrict__ tt, const float* __restrict__ ew,
                          const float* __restrict__ ent, const float* __restrict__ rel,
                          const float* __restrict__ tim,
                          float* __restrict__ sums, float* __restrict__ cnt, int E) {
    int e = (int)(((size_t)blockIdx.x * blockDim.x + threadIdx.x) >> 5);
    if (e >= E) return;
    int lane = threadIdx.x & 31;
    int src = ei[e], dst = ei[E + e];
    int r = et[e], ti = tt[e];
    float w = ew[e];
    float4 a = ((const float4*)(ent + (size_t)src * DIM))[lane];
    float4 b = ((const float4*)(rel + (size_t)r * DIM))[lane];
    float4 c = ((const float4*)(tim + (size_t)ti * DIM))[lane];
    float4 m;
    m.x = (a.x + b.x + c.x) * w;
    m.y = (a.y + b.y + c.y) * w;
    m.z = (a.z + b.z + c.z) * w;
    m.w = (a.w + b.w + c.w) * w;
    atomicAdd(((float4*)(sums + (size_t)dst * DIM)) + lane, m);
    if (lane == 0) atomicAdd(cnt + dst, w);
}

// warp-per-row: mean, L2-normalize, permute-gather
__global__ void k_normperm(const int* __restrict__ perm, const float* __restrict__ sums,
                           const float* __restrict__ cnt, float* __restrict__ xo, int N) {
    int row = (int)(((size_t)blockIdx.x * blockDim.x + threadIdx.x) >> 5);
    if (row >= N) return;
    int lane = threadIdx.x & 31;
    int p = perm[row];
    float inv = 1.f / fmaxf(cnt[p], 1.f);
    float4 v = ((const float4*)(sums + (size_t)p * DIM))[lane];
    v.x *= inv; v.y *= inv; v.z *= inv; v.w *= inv;
    float sq = v.x * v.x + v.y * v.y + v.z * v.z + v.w * v.w;
#pragma unroll
    for (int o = 16; o > 0; o >>= 1) sq += __shfl_xor_sync(0xffffffffu, sq, o);
    float s = 1.f / fmaxf(sqrtf(sq), 1e-12f);
    v.x *= s; v.y *= s; v.z *= s; v.w *= s;
    ((float4*)(xo + (size_t)row * DIM))[lane] = v;
}

__device__ __forceinline__ float sigmoidf_fast(float v) {
    return 1.f / (1.f + __expf(-v));
}

// zg = x @ Wi + bi ; a = sigmoid(g)*A ; b = B*z ; fused per-64-row-chunk (P,Q).
// Tile = 64 rows = 1 chunk. 256 threads: warp wid covers rows wid*8..+8,
// lane jg covers z cols jg*4..+4 and g cols 128+jg*4..+4.
// x tile TRANSPOSED in smem (stride 68) -> row-pair f32x2 packing, W dup'd via movs.
__global__ void __launch_bounds__(256, 1) k_inproj(
    const float* __restrict__ x, const float* __restrict__ Wi, const float* __restrict__ bi,
    const float* __restrict__ Av, const float* __restrict__ Bv,
    float* __restrict__ aout, float* __restrict__ bout,
    float* __restrict__ Pb, float* __restrict__ Qb, int N, int NC) {
    extern __shared__ __align__(16) char smraw[];
    float* w_sm = (float*)smraw;                       // 32768 f = 131072 B
    float* x_ts = (float*)(smraw + 131072);            // 128*68 = 8704 f = 34816 B
    float* bi_sm = (float*)(smraw + 131072 + 34816);   // 256 f
    float* A_sm = bi_sm + 256;                         // 128 f
    float* B_sm = A_sm + 128;                          // 128 f
    float* pq_sm = B_sm + 128;                         // 2048 f (P[8][128], Q at +1024)
    int t = threadIdx.x;
    for (int k = t; k < 8192; k += 256) ((float4*)w_sm)[k] = ((const float4*)Wi)[k];
    if (t < 64) ((float4*)bi_sm)[t] = ((const float4*)bi)[t];
    if (t < 32) ((float4*)A_sm)[t] = ((const float4*)Av)[t];
    else if (t < 64) ((float4*)B_sm)[t - 32] = ((const float4*)Bv)[t - 32];
    __syncthreads();
    int jg = t & 31, wid = t >> 5;
    for (int tile = blockIdx.x; tile < NC; tile += gridDim.x) {
        int row0 = tile << 6;
        __syncthreads();
        // stage x transposed: x_ts[d*68 + r]
        for (int k = t; k < 2048; k += 256) {
            int c4 = k >> 6;     // 0..31 (float4 column)
            int r = k & 63;      // row in tile
            float4 v = make_float4(0.f, 0.f, 0.f, 0.f);
            if (row0 + r < N) v = ((const float4*)x)[(size_t)(row0 + r) * 32 + c4];
            x_ts[(4 * c4 + 0) * 68 + r] = v.x;
            x_ts[(4 * c4 + 1) * 68 + r] = v.y;
            x_ts[(4 * c4 + 2) * 68 + r] = v.z;
            x_ts[(4 * c4 + 3) * 68 + r] = v.w;
        }
        __syncthreads();
        u64 az[4][4], ag[4][4];   // [col j][row pair]
#pragma unroll
        for (int c = 0; c < 4; c++)
#pragma unroll
            for (int rp = 0; rp < 4; rp++) { az[c][rp] = 0ull; ag[c][rp] = 0ull; }
#pragma unroll 2
        for (int d = 0; d < DIM; d++) {
            float4 wz4 = *(const float4*)(w_sm + d * 256 + jg * 4);
            float4 wg4 = *(const float4*)(w_sm + d * 256 + 128 + jg * 4);
            u64 wz[4] = {dup2(wz4.x), dup2(wz4.y), dup2(wz4.z), dup2(wz4.w)};
            u64 wg[4] = {dup2(wg4.x), dup2(wg4.y), dup2(wg4.z), dup2(wg4.w)};
            const float* xb = x_ts + d * 68 + (wid << 3);
            ulonglong2 xp01 = *(const ulonglong2*)(xb);       // rows {0,1},{2,3}
            ulonglong2 xp23 = *(const ulonglong2*)(xb + 4);   // rows {4,5},{6,7}
            u64 xp[4] = {xp01.x, xp01.y, xp23.x, xp23.y};
#pragma unroll
            for (int c = 0; c < 4; c++)
#pragma unroll
                for (int rp = 0; rp < 4; rp++) {
                    fma2(az[c][rp], wz[c], xp[rp]);
                    fma2(ag[c][rp], wg[c], xp[rp]);
                }
        }
        float4 bz = ((const float4*)bi_sm)[jg];
        float4 bg = ((const float4*)bi_sm)[jg + 32];
        float4 B4 = ((const float4*)B_sm)[jg];
        float4 A4 = ((const float4*)A_sm)[jg];
        float p0 = 1.f, p1 = 1.f, p2 = 1.f, p3 = 1.f;
        float q0 = 0.f, q1 = 0.f, q2 = 0.f, q3 = 0.f;
#pragma unroll
        for (int rp = 0; rp < 4; rp++) {
            float2 zu[4], gu[4];
#pragma unroll
            for (int c = 0; c < 4; c++) { zu[c] = unpack2(az[c][rp]); gu[c] = unpack2(ag[c][rp]); }
#pragma unroll
            for (int i = 0; i < 2; i++) {   // ascending rows within pair
                int row = row0 + (wid << 3) + rp * 2 + i;
                float zz0 = i ? zu[0].y : zu[0].x, zz1 = i ? zu[1].y : zu[1].x;
                float zz2 = i ? zu[2].y : zu[2].x, zz3 = i ? zu[3].y : zu[3].x;
                float gg0 = i ? gu[0].y : gu[0].x, gg1 = i ? gu[1].y : gu[1].x;
                float gg2 = i ? gu[2].y : gu[2].x, gg3 = i ? gu[3].y : gu[3].x;
                float4 ob, oa;
                ob.x = B4.x * (zz0 + bz.x);
                ob.y = B4.y * (zz1 + bz.y);
                ob.z = B4.z * (zz2 + bz.z);
                ob.w = B4.w * (zz3 + bz.w);
                oa.x = A4.x * sigmoidf_fast(gg0 + bg.x);
                oa.y = A4.y * sigmoidf_fast(gg1 + bg.y);
                oa.z = A4.z * sigmoidf_fast(gg2 + bg.z);
                oa.w = A4.w * sigmoidf_fast(gg3 + bg.w);
                if (row < N) {
                    ((float4*)(bout + (size_t)row * DIM))[jg] = ob;
                    ((float4*)(aout + (size_t)row * DIM))[jg] = oa;
                } else {
                    oa = make_float4(1.f, 1.f, 1.f, 1.f);
                    ob = make_float4(0.f, 0.f, 0.f, 0.f);
                }
                q0 = fmaf(oa.x, q0, ob.x); p0 *= oa.x;
                q1 = fmaf(oa.y, q1, ob.y); p1 *= oa.y;
                q2 = fmaf(oa.z, q2, ob.z); p2 *= oa.z;
                q3 = fmaf(oa.w, q3, ob.w); p3 *= oa.w;
            }
        }
        ((float4*)(pq_sm + wid * 128))[jg] = make_float4(p0, p1, p2, p3);
        ((float4*)(pq_sm + 1024 + wid * 128))[jg] = make_float4(q0, q1, q2, q3);
        __syncthreads();
        if (t < 128) {   // compose 8 warp-partials (ascending row-groups)
            float P = 1.f, Q = 0.f;
#pragma unroll
            for (int s = 0; s < 8; s++) {
                float pp = pq_sm[s * 128 + t];
                float qq = pq_sm[1024 + s * 128 + t];
                Q = fmaf(pp, Q, qq);
                P *= pp;
            }
            Pb[(size_t)tile * DIM + t] = P;
            Qb[(size_t)tile * DIM + t] = Q;
        }
    }
}

// compose 64-row-chunk carries (single block; smem-staged, register-grouped chain)
__global__ void k_carry(const float* __restrict__ P, const float* __restrict__ Q,
                        float* __restrict__ C, int NC) {
    extern __shared__ float sm[];
    float* Ps = sm;
    float* Qs = sm + 64 * DIM;
    int d = threadIdx.x;
    float h = 0.f;
    for (int base = 0; base < NC; base += 64) {
        int cnt = min(64, NC - base);
        __syncthreads();
        for (int k = d; k < cnt * DIM; k += DIM) {
            Ps[k] = P[base * DIM + k];
            Qs[k] = Q[base * DIM + k];
        }
        __syncthreads();
        for (int k0 = 0; k0 < cnt; k0 += 4) {
            float p[4], q[4];
#pragma unroll
            for (int j = 0; j < 4; j++) {
                if (k0 + j < cnt) {
                    p[j] = Ps[(k0 + j) * DIM + d];
                    q[j] = Qs[(k0 + j) * DIM + d];
                } else { p[j] = 1.f; q[j] = 0.f; }
            }
#pragma unroll
            for (int j = 0; j < 4; j++) {
                if (k0 + j < cnt) C[(size_t)(base + k0 + j) * DIM + d] = h;
                h = fmaf(p[j], h, q[j]);
            }
        }
    }
}

// replay 64-row chunk with carry; emit h in per-tile TRANSPOSED layout h_t[tile][d][64]
__global__ void k_scan2(const float* __restrict__ a, const float* __restrict__ b,
                        const float* __restrict__ C, float* __restrict__ h_t) {
    __shared__ float hs[128 * 68];
    int c = blockIdx.x, d = threadIdx.x;
    float hv = C[(size_t)c * DIM + d];
    size_t base = (size_t)c * 64 * DIM + d;
#pragma unroll 8
    for (int r = 0; r < 64; r++) {
        hv = fmaf(a[base + (size_t)r * DIM], hv, b[base + (size_t)r * DIM]);
        hs[d * 68 + r] = hv;
    }
    __syncthreads();
    float4* out = (float4*)(h_t + (size_t)c * 8192);
    for (int k = d; k < 2048; k += 128) {
        int dd = k >> 4;            // d index
        int r4 = (k & 15) * 4;      // row*4
        out[k] = *(const float4*)(hs + dd * 68 + r4);
    }
}

// y = x + h@Wo + bo ; LayerNorm -> xo. Tile = 64 rows; h from transposed h_t.
// 256 threads: warp wid covers rows wid*8..+8; lane covers cols lane*4..+4.
__global__ void __launch_bounds__(256, 2) k_outproj(
    const float* __restrict__ x, const float* __restrict__ h_t,
    const float* __restrict__ Wo, const float* __restrict__ bo,
    const float* __restrict__ lng, const float* __restrict__ lnb,
    float* __restrict__ xo, int N, int NC) {
    extern __shared__ __align__(16) char smraw[];
    float* w_sm = (float*)smraw;                       // 16384 f = 65536 B
    float* h_ts = (float*)(smraw + 65536);             // 128*68 f = 34816 B
    float* bo_sm = (float*)(smraw + 65536 + 34816);    // 128 f
    float* g_sm = bo_sm + 128;
    float* be_sm = g_sm + 128;
    int t = threadIdx.x;
    for (int k = t; k < 4096; k += 256) ((float4*)w_sm)[k] = ((const float4*)Wo)[k];
    if (t < 32) ((float4*)bo_sm)[t] = ((const float4*)bo)[t];
    else if (t < 64) ((float4*)g_sm)[t - 32] = ((const float4*)lng)[t - 32];
    else if (t < 96) ((float4*)be_sm)[t - 64] = ((const float4*)lnb)[t - 64];
    __syncthreads();
    int lane = t & 31, wid = t >> 5;
    for (int tile = blockIdx.x; tile < NC; tile += gridDim.x) {
        int row0 = tile << 6;
        __syncthreads();
        for (int k = t; k < 2048; k += 256) {   // coalesced load of transposed tile
            float4 v = ((const float4*)(h_t + (size_t)tile * 8192))[k];
            int dd = k >> 4;
            int r4 = (k & 15) * 4;
            *(float4*)(h_ts + dd * 68 + r4) = v;
        }
        __syncthreads();
        u64 acc[4][4];   // [col j][row pair]
#pragma unroll
        for (int c = 0; c < 4; c++)
#pragma unroll
            for (int rp = 0; rp < 4; rp++) acc[c][rp] = 0ull;
#pragma unroll 2
        for (int d = 0; d < DIM; d++) {
            float4 w4 = *(const float4*)(w_sm + d * 128 + lane * 4);
            u64 wd[4] = {dup2(w4.x), dup2(w4.y), dup2(w4.z), dup2(w4.w)};
            const float* hb = h_ts + d * 68 + (wid << 3);
            ulonglong2 hp01 = *(const ulonglong2*)(hb);
            ulonglong2 hp23 = *(const ulonglong2*)(hb + 4);
            u64 hp[4] = {hp01.x, hp01.y, hp23.x, hp23.y};
#pragma unroll
            for (int c = 0; c < 4; c++)
#pragma unroll
                for (int rp = 0; rp < 4; rp++)
                    fma2(acc[c][rp], wd[c], hp[rp]);
        }
        float4 b4 = ((const float4*)bo_sm)[lane];
        float4 g4 = ((const float4*)g_sm)[lane];
        float4 e4 = ((const float4*)be_sm)[lane];
#pragma unroll
        for (int rp = 0; rp < 4; rp++) {
            float2 au[4];
#pragma unroll
            for (int c = 0; c < 4; c++) au[c] = unpack2(acc[c][rp]);
#pragma unroll
            for (int i = 0; i < 2; i++) {
                int row = row0 + (wid << 3) + rp * 2 + i;
                if (row < N) {   // uniform across warp
                    float4 xv = ((const float4*)x)[(size_t)row * 32 + lane];
                    float4 y;
                    y.x = (i ? au[0].y : au[0].x) + b4.x + xv.x;
                    y.y = (i ? au[1].y : au[1].x) + b4.y + xv.y;
                    y.z = (i ? au[2].y : au[2].x) + b4.z + xv.z;
                    y.w = (i ? au[3].y : au[3].x) + b4.w + xv.w;
                    float s = y.x + y.y + y.z + y.w;
                    float sq = y.x * y.x + y.y * y.y + y.z * y.z + y.w * y.w;
#pragma unroll
                    for (int o = 16; o > 0; o >>= 1) {
                        s += __shfl_xor_sync(0xffffffffu, s, o);
                        sq += __shfl_xor_sync(0xffffffffu, sq, o);
                    }
                    float mu = s * (1.f / 128.f);
                    float var = sq * (1.f / 128.f) - mu * mu;
                    float rs = rsqrtf(var + 1e-5f);
                    float4 o4;
                    o4.x = (y.x - mu) * rs * g4.x + e4.x;
                    o4.y = (y.y - mu) * rs * g4.y + e4.y;
                    o4.z = (y.z - mu) * rs * g4.z + e4.z;
                    o4.w = (y.w - mu) * rs * g4.w + e4.w;
                    ((float4*)(xo + (size_t)row * DIM))[lane] = o4;
                }
            }
        }
    }
}

// ---------------- launch ----------------
static constexpr int SMEM_IN = 131072 + 34816 + (256 + 128 + 128 + 2048) * 4;  // 176,128 B
static constexpr int SMEM_OUT = 65536 + 34816 + (128 + 128 + 128) * 4;         // 101,888 B

extern "C" void kernel_launch(void* const* d_in, const int* in_sizes, int n_in,
                              void* d_out, int out_size) {
    const int* edge_index = (const int*)d_in[0];
    const int* edge_type = (const int*)d_in[1];
    const int* edge_time = (const int*)d_in[2];
    const float* edge_weight = (const float*)d_in[3];
    const int* perm = (const int*)d_in[4];
    const float* ent = (const float*)d_in[5];
    const float* rel = (const float*)d_in[6];
    const float* tim = (const float*)d_in[7];
    const float* Wi = (const float*)d_in[8];
    const float* bi = (const float*)d_in[9];
    const float* Wo = (const float*)d_in[10];
    const float* bo = (const float*)d_in[11];
    const float* Av = (const float*)d_in[12];
    const float* Bv = (const float*)d_in[13];
    const float* lng = (const float*)d_in[14];
    const float* lnb = (const float*)d_in[15];
    float* out = (float*)d_out;

    int E = in_sizes[1];
    int N = in_sizes[4];
    int L = in_sizes[12] / DIM;

    float* base = nullptr;
    cudaGetSymbolAddress((void**)&base, g_scratch);
    float* sums = base + OFF_SUMS;
    float* cnt = base + OFF_CNT;
    float* x0 = base + OFF_X0;
    float* x1 = base + OFF_X1;
    float* ab_a = base + OFF_A;
    float* ab_b = base + OFF_B;
    float* h_t = base + OFF_HT;
    float* Pb = base + OFF_P;
    float* Qb = base + OFF_Q;
    float* Cb = base + OFF_C;

    cudaFuncSetAttribute(k_inproj, cudaFuncAttributeMaxDynamicSharedMemorySize, SMEM_IN);
    cudaFuncSetAttribute(k_outproj, cudaFuncAttributeMaxDynamicSharedMemorySize, SMEM_OUT);
    cudaFuncSetAttribute(k_carry, cudaFuncAttributeMaxDynamicSharedMemorySize, 65536);

    k_zero<<<2048, 256>>>(sums, cnt, N);

    int sblocks = (int)(((size_t)E * 32 + 255) / 256);
    k_scatter<<<sblocks, 256>>>(edge_index, edge_type, edge_time, edge_weight,
                                ent, rel, tim, sums, cnt, E);

    k_normperm<<<(N + 7) / 8, 256>>>(perm, sums, cnt, x0, N);

    int NC = (N + 63) / 64;   // 64-row chunks == GEMM tiles
    float* ping[2] = {x0, x1};
    const float* xin = x0;
    for (int l = 0; l < L; l++) {
        k_inproj<<<148, 256, SMEM_IN>>>(xin, Wi + (size_t)l * DIM * 2 * DIM,
                                        bi + (size_t)l * 2 * DIM,
                                        Av + (size_t)l * DIM, Bv + (size_t)l * DIM,
                                        ab_a, ab_b, Pb, Qb, N, NC);
        k_carry<<<1, DIM, 65536>>>(Pb, Qb, Cb, NC);
        k_scan2<<<NC, DIM>>>(ab_a, ab_b, Cb, h_t);
        float* xout = (l == L - 1) ? out : ping[(l + 1) & 1];
        k_outproj<<<296, 256, SMEM_OUT>>>(xin, h_t, Wo + (size_t)l * DIM * DIM,
                                          bo + (size_t)l * DIM,
                                          lng + (size_t)l * DIM, lnb + (size_t)l * DIM,
                                          xout, N, NC);
        xin = xout;
    }
}